// round 1
// baseline (speedup 1.0000x reference)
#include <cuda_runtime.h>

#define NXX 64
#define HIDD 16
#define DTT 1e-4f

// tanh(x) = 1 - 2/(exp(2x)+1), via ex2.approx + rcp.approx.
// Max error ~1e-6; saturates correctly: x->+inf => ex2->inf, rcp(inf)=0 => 1;
// x->-inf => ex2->0, rcp(1)=1 => -1.
__device__ __forceinline__ float tanh_fast(float x) {
    float e;
    asm("ex2.approx.f32 %0, %1;" : "=f"(e) : "f"(x * 2.88539008177792681472f)); // 2*log2(e)
    float r;
    asm("rcp.approx.f32 %0, %1;" : "=f"(r) : "f"(e + 1.0f));
    return fmaf(-2.0f, r, 1.0f);
}

// 256 threads: 4 lanes per grid point (p = tid>>2, s = tid&3).
// Lane s owns hidden units m = s*8 .. s*8+7 (m<16 -> layer 1, else layer 2).
// Partial head dot-products combined with shfl_xor within the 4-lane group.
// Ping-pong u buffers in SMEM -> exactly one __syncthreads per timestep.
__global__ __launch_bounds__(256, 1) void scct_kernel(
    const float* __restrict__ u0,  const float* __restrict__ w1,
    const float* __restrict__ b1,  const float* __restrict__ w2,
    const float* __restrict__ b2,  const float* __restrict__ wc,
    const float* __restrict__ bc,  const float* __restrict__ gamma_p,
    const int*   __restrict__ nt_p, float* __restrict__ out)
{
    __shared__ float ub[2][NXX];

    const int tid = threadIdx.x;
    const int p = tid >> 2;   // grid point 0..63
    const int s = tid & 3;    // hidden-unit sub-slot 0..3

    // Load this lane's 8 hidden units into registers.
    float Wu[8], Wg[8], Wl[8], Bq[8], Cq[8];
    const float* wsel = (s < 2) ? w1 : w2;
    const float* bsel = (s < 2) ? b1 : b2;
    const int jbase = (s & 1) * 8;
#pragma unroll
    for (int q = 0; q < 8; q++) {
        int j = jbase + q;          // row within selected layer
        int m = s * 8 + q;          // index into wc (0..31)
        Wu[q] = wsel[j * 3 + 0];
        Wg[q] = wsel[j * 3 + 1];
        Wl[q] = wsel[j * 3 + 2];
        Bq[q] = bsel[j];
        Cq[q] = wc[m];
    }
    const float gmm = *gamma_p;
    const float bcv = *bc;
    const int Nt = *nt_p;

    if (tid < NXX) ub[0][tid] = u0[tid];
    __syncthreads();

    // DX = 1/63: 1/(2DX) = 31.5 exact, 1/DX^2 ~= 3969 (1-ulp of ref's f32 divide)
    const float INV2DX = 31.5f;
    const float INVDX2 = 3969.0f;

    const bool interior = (p > 0) && (p < NXX - 1);
    const int pm = (p == 0) ? 0 : p - 1;
    const int pp = (p == NXX - 1) ? NXX - 1 : p + 1;

    int cur = 0;
    for (int it = 0; it < Nt; ++it) {
        const float uc = ub[cur][p];
        const float um = ub[cur][pm];
        const float up = ub[cur][pp];

        float gx = 0.0f, lx = 0.0f;
        if (interior) {
            gx = (up - um) * INV2DX;
            lx = ((up - 2.0f * uc) + um) * INVDX2;
        }

        // Partial head dot product over this lane's 8 hidden units.
        float acc = (s == 0) ? bcv : 0.0f;
#pragma unroll
        for (int q = 0; q < 8; q++) {
            float z = fmaf(Wl[q], lx, Bq[q]);
            z = fmaf(Wg[q], gx, z);
            z = fmaf(Wu[q], uc, z);
            acc = fmaf(Cq[q], tanh_fast(z), acc);
        }
        // Butterfly-combine the 4 partials of this point (same warp, lanes 4k..4k+3).
        acc += __shfl_xor_sync(0xffffffffu, acc, 1);
        acc += __shfl_xor_sync(0xffffffffu, acc, 2);

        if (s == 0) {
            float u3   = uc * uc * uc;
            float core = 0.8f * lx + 0.5f * uc - u3;
            float rhs  = fmaf(gmm, acc, core);
            float un   = fmaf(DTT, rhs, uc);
            ub[cur ^ 1][p] = interior ? un : 0.0f;
        }
        __syncthreads();
        cur ^= 1;
    }

    // ---- epilogue: u, phi2, entropy of 64-bin histogram of |u|/max ----
    if (tid < NXX) out[tid] = ub[cur][tid];

    if (tid == 0) {
        const float* uf = ub[cur];
        float s2 = 0.0f, vmax = 0.0f;
        for (int i = 0; i < NXX; i++) {
            float u = uf[i];
            s2 += u * u;
            vmax = fmaxf(vmax, fabsf(u));
        }
        float phi2 = s2 * (1.0f / 64.0f);

        int hist[64];
#pragma unroll
        for (int i = 0; i < 64; i++) hist[i] = 0;
        float denom = fmaxf(vmax, 1e-12f);
        for (int i = 0; i < NXX; i++) {
            float vn = fabsf(uf[i]) / denom;   // IEEE f32 div, matches ref
            int b = (int)(vn * 64.0f);         // exact *64 => half-open bins match
            if (b > 63) b = 63;                // right-closed last bin
            hist[b]++;
        }
        float H = 0.0f;
        for (int i = 0; i < 64; i++) {
            if (hist[i] > 0) {
                float pb = (float)hist[i] * (1.0f / 64.0f);
                H -= pb * logf(pb);            // pb + 1e-12 == pb in f32
            }
        }
        if (vmax < 1e-12f) H = 0.0f;
        out[64] = phi2;
        out[65] = H;
    }
}

extern "C" void kernel_launch(void* const* d_in, const int* in_sizes, int n_in,
                              void* d_out, int out_size) {
    (void)in_sizes; (void)n_in; (void)out_size;
    scct_kernel<<<1, 256>>>(
        (const float*)d_in[0],  // u0
        (const float*)d_in[1],  // w1
        (const float*)d_in[2],  // b1
        (const float*)d_in[3],  // w2
        (const float*)d_in[4],  // b2
        (const float*)d_in[5],  // wc
        (const float*)d_in[6],  // bc
        (const float*)d_in[7],  // gamma
        (const int*)  d_in[8],  // Nt
        (float*)d_out);
}

// round 3
// speedup vs baseline: 1.2650x; 1.2650x over previous
#include <cuda_runtime.h>

#define NXX 64
#define DTT 1e-4f

__device__ __forceinline__ float ex2_fast(float x) {
    float e;
    asm("ex2.approx.f32 %0, %1;" : "=f"(e) : "f"(x));
    return e;
}
__device__ __forceinline__ float rcp_fast(float x) {
    float r;
    asm("rcp.approx.f32 %0, %1;" : "=f"(r) : "f"(x));
    return r;
}

// 128 threads: 2 lanes per grid point (p = tid>>1, s = tid&1).
// Lane s owns one full 16-unit layer (s=0 -> layer1, s=1 -> layer2).
// tanh(x) = 1 - 2/(e^{2x}+1); e^{2x} = 2^{K x} with K=2*log2(e) folded into
// the weights. Head folded: sum wc_m*tanh_m + bc = (sum wc + bc) + sum (-2 wc_m) r_m.
// Reciprocals computed in PAIRS: r = rcp(a0*a1); 1/a0 = r*a1; 1/a1 = r*a0
// (halves MUFU rcp count; z clamped to +-63 so a in [1, 2^63] and the pair
// product never overflows -> no inf/NaN path, saturation exact).
// uc carried in registers (both lanes recompute u_new after one shfl_xor);
// SMEM ping-pong only for neighbor exchange -> one barrier per step.
__global__ __launch_bounds__(128, 1) void scct_kernel(
    const float* __restrict__ u0,  const float* __restrict__ w1,
    const float* __restrict__ b1,  const float* __restrict__ w2,
    const float* __restrict__ b2,  const float* __restrict__ wc,
    const float* __restrict__ bc,  const float* __restrict__ gamma_p,
    const int*   __restrict__ nt_p, float* __restrict__ out)
{
    __shared__ float ub[2][NXX];

    const int tid = threadIdx.x;
    const int p = tid >> 1;   // grid point 0..63
    const int s = tid & 1;    // layer select

    const float K = 2.88539008177792681472f;  // 2*log2(e)

    float Wu[16], Wg[16], Wl[16], Bq[16], Cq[16];
    const float* wsel = s ? w2 : w1;
    const float* bsel = s ? b2 : b1;
    float csum = 0.0f;
#pragma unroll
    for (int q = 0; q < 16; q++) {
        Wu[q] = wsel[q * 3 + 0] * K;
        Wg[q] = wsel[q * 3 + 1] * K;
        Wl[q] = wsel[q * 3 + 2] * K;
        Bq[q] = bsel[q] * K;
        float c = wc[s * 16 + q];
        Cq[q] = -2.0f * c;
        csum += c;
    }
    // Stot = sum of ALL 32 wc + bc (both lanes hold the full constant).
    float Stot = csum + __shfl_xor_sync(0xffffffffu, csum, 1) + *bc;

    const float gmm = *gamma_p;
    const int Nt = *nt_p;

    if (tid < NXX) ub[0][tid] = u0[tid];
    __syncthreads();

    const float INV2DX = 31.5f;    // 63/2 exact
    const float INVDX2 = 3969.0f;  // 63^2

    const bool interior = (p > 0) && (p < NXX - 1);
    const int pm = (p == 0) ? 0 : p - 1;
    const int pp = (p == NXX - 1) ? NXX - 1 : p + 1;

    float uc = ub[0][p];
    int cur = 0;

    for (int it = 0; it < Nt; ++it) {
        const float um = ub[cur][pm];
        const float up = ub[cur][pp];

        float gx = 0.0f, lx = 0.0f;
        if (interior) {
            gx = (up - um) * INV2DX;
            lx = ((up - 2.0f * uc) + um) * INVDX2;
        }

        float P0 = 0.0f, P1 = 0.0f;
#pragma unroll
        for (int j = 0; j < 8; j++) {
            const int q0 = 2 * j, q1 = 2 * j + 1;
            float z0 = fmaf(Wu[q0], uc, fmaf(Wg[q0], gx, fmaf(Wl[q0], lx, Bq[q0])));
            float z1 = fmaf(Wu[q1], uc, fmaf(Wg[q1], gx, fmaf(Wl[q1], lx, Bq[q1])));
            z0 = fminf(fmaxf(z0, -63.0f), 63.0f);
            z1 = fminf(fmaxf(z1, -63.0f), 63.0f);
            float a0 = ex2_fast(z0) + 1.0f;   // in [1, 2^63]
            float a1 = ex2_fast(z1) + 1.0f;
            float r  = rcp_fast(a0 * a1);     // product <= ~2^126: no overflow
            P0 = fmaf(Cq[q0], r * a1, P0);    // Cq = -2*wc  ->  -2*wc/a0
            P1 = fmaf(Cq[q1], r * a0, P1);
        }
        float P = P0 + P1;
        P += __shfl_xor_sync(0xffffffffu, P, 1);   // both lanes get full head sum
        const float mlp = Stot + P;

        const float u3   = uc * uc * uc;
        const float core = fmaf(0.8f, lx, fmaf(0.5f, uc, -u3));
        const float rhs  = fmaf(gmm, mlp, core);
        float un = fmaf(DTT, rhs, uc);
        un = interior ? un : 0.0f;

        if (s == 0) ub[cur ^ 1][p] = un;
        __syncthreads();
        uc = un;
        cur ^= 1;
    }

    // ---- epilogue: u, phi2, entropy of 64-bin histogram of |u|/max ----
    if (tid < NXX) out[tid] = ub[cur][tid];

    if (tid == 0) {
        const float* uf = ub[cur];
        float s2 = 0.0f, vmax = 0.0f;
        for (int i = 0; i < NXX; i++) {
            float u = uf[i];
            s2 += u * u;
            vmax = fmaxf(vmax, fabsf(u));
        }
        float phi2 = s2 * (1.0f / 64.0f);

        int hist[64];
#pragma unroll
        for (int i = 0; i < 64; i++) hist[i] = 0;
        float denom = fmaxf(vmax, 1e-12f);
        for (int i = 0; i < NXX; i++) {
            float vn = fabsf(uf[i]) / denom;   // IEEE div, matches ref
            int b = (int)(vn * 64.0f);
            if (b > 63) b = 63;
            hist[b]++;
        }
        float H = 0.0f;
        for (int i = 0; i < 64; i++) {
            if (hist[i] > 0) {
                float pb = (float)hist[i] * (1.0f / 64.0f);
                H -= pb * logf(pb);
            }
        }
        if (vmax < 1e-12f) H = 0.0f;
        out[64] = phi2;
        out[65] = H;
    }
}

extern "C" void kernel_launch(void* const* d_in, const int* in_sizes, int n_in,
                              void* d_out, int out_size) {
    (void)in_sizes; (void)n_in; (void)out_size;
    scct_kernel<<<1, 128>>>(
        (const float*)d_in[0],  // u0
        (const float*)d_in[1],  // w1
        (const float*)d_in[2],  // b1
        (const float*)d_in[3],  // w2
        (const float*)d_in[4],  // b2
        (const float*)d_in[5],  // wc
        (const float*)d_in[6],  // bc
        (const float*)d_in[7],  // gamma
        (const int*)  d_in[8],  // Nt
        (float*)d_out);
}